// round 16
// baseline (speedup 1.0000x reference)
#include <cuda_runtime.h>
#include <cuda_bf16.h>
#include <cooperative_groups.h>
#include <cstdint>
#include <cstddef>

namespace cg = cooperative_groups;

#define N_JOBS 100000
#define N_MACH 10000
#define DIM 128
#define KDIM 256
#define BM 64
#define THREADS_T 512
#define LN_EPS 1e-5f
#define MAX_EDGES 1600000

#define JOB_TILES ((N_JOBS + BM - 1) / BM)    // 1563
#define MACH_TILES ((N_MACH + BM - 1) / BM)   // 157

#define SCAN_CHUNK 512
#define JB ((N_JOBS + SCAN_CHUNK - 1) / SCAN_CHUNK)   // 196
#define MB ((N_MACH + SCAN_CHUNK - 1) / SCAN_CHUNK)   // 20

// smem layout. W rows 528B stride, A rows 272B stride (both +4-bank/row ->
// conflict-free ldmatrix). Double-buffered A halves (hi+lo each).
#define SM_BIAS 16
#define SM_GS   528
#define SM_GB   1040
#define SM_PART 2048                       // 64 rows x 4 quarters x float2 = 2KB
#define SM_WHI  4096
#define SM_WLO  (SM_WHI + 128 * 528)       //  71680
#define SM_A0HI (SM_WLO + 128 * 528)       // 139264
#define SM_A0LO (SM_A0HI + 64 * 272)       // 156672
#define SM_A1HI (SM_A0LO + 64 * 272)       // 174080
#define SM_A1LO (SM_A1HI + 64 * 272)       // 191488
#define SM_TOTAL (SM_A1LO + 64 * 272)      // 208896

// Scratch device globals: CSR ~14MB + bf16 hi/lo tables ~112MB.
__device__ int g_job_off[N_JOBS + 1];
__device__ int g_mach_off[N_MACH + 1];
__device__ int g_job_cur[N_JOBS];
__device__ int g_mach_cur[N_MACH];
__device__ int g_job_nbr[MAX_EDGES];
__device__ int g_mach_nbr[MAX_EDGES];
__device__ int g_bsum[JB + MB];
__device__ __align__(256) __nv_bfloat16 g_job_hi[(size_t)N_JOBS * DIM];
__device__ __align__(256) __nv_bfloat16 g_job_lo[(size_t)N_JOBS * DIM];
__device__ __align__(256) __nv_bfloat16 g_mach_hi[(size_t)N_MACH * DIM];
__device__ __align__(256) __nv_bfloat16 g_mach_lo[(size_t)N_MACH * DIM];
__device__ __align__(256) __nv_bfloat16 g_jagg_hi[(size_t)N_JOBS * DIM];
__device__ __align__(256) __nv_bfloat16 g_jagg_lo[(size_t)N_JOBS * DIM];
__device__ __align__(256) __nv_bfloat16 g_magg_hi[(size_t)N_MACH * DIM];
__device__ __align__(256) __nv_bfloat16 g_magg_lo[(size_t)N_MACH * DIM];

// ---------------- helpers ----------------------------------------------------
__device__ __forceinline__ uint32_t smem_to_u32(const void* p) {
    uint32_t a;
    asm("{ .reg .u64 t; cvta.to.shared.u64 t, %1; cvt.u32.u64 %0, t; }" : "=r"(a) : "l"(p));
    return a;
}
__device__ __forceinline__ void ldsm_x4(uint32_t* r, uint32_t addr) {
    asm volatile("ldmatrix.sync.aligned.m8n8.x4.shared.b16 {%0,%1,%2,%3}, [%4];"
        : "=r"(r[0]), "=r"(r[1]), "=r"(r[2]), "=r"(r[3]) : "r"(addr));
}
__device__ __forceinline__ void mma_bf16(float* c, const uint32_t* a, const uint32_t* b) {
    asm volatile(
        "mma.sync.aligned.m16n8k16.row.col.f32.bf16.bf16.f32 "
        "{%0,%1,%2,%3}, {%4,%5,%6,%7}, {%8,%9}, {%0,%1,%2,%3};"
        : "+f"(c[0]), "+f"(c[1]), "+f"(c[2]), "+f"(c[3])
        : "r"(a[0]), "r"(a[1]), "r"(a[2]), "r"(a[3]), "r"(b[0]), "r"(b[1]));
}
__device__ __forceinline__ void cp_async16(uint32_t dst, const void* src) {
    asm volatile("cp.async.cg.shared.global [%0], [%1], 16;" :: "r"(dst), "l"(src));
}
// fp32x4 -> hi bf16x4 + lo bf16x4 (lo = round(x - hi)).
__device__ __forceinline__ void split_bf16(float4 v, uint2& H, uint2& L) {
    __nv_bfloat162 h01 = __floats2bfloat162_rn(v.x, v.y);
    __nv_bfloat162 h23 = __floats2bfloat162_rn(v.z, v.w);
    float2 f01 = __bfloat1622float2(h01);
    float2 f23 = __bfloat1622float2(h23);
    __nv_bfloat162 l01 = __floats2bfloat162_rn(v.x - f01.x, v.y - f01.y);
    __nv_bfloat162 l23 = __floats2bfloat162_rn(v.z - f23.x, v.w - f23.y);
    H.x = *(unsigned*)&h01; H.y = *(unsigned*)&h23;
    L.x = *(unsigned*)&l01; L.y = *(unsigned*)&l23;
}

// ---------------- convert h tables to bf16 hi/lo -----------------------------
__global__ void convert_kernel(const float* __restrict__ job_h,
                               const float* __restrict__ machine_h) {
    int i = blockIdx.x * blockDim.x + threadIdx.x;
    int stride = gridDim.x * blockDim.x;
    const int nj = N_JOBS * DIM / 4, nm = N_MACH * DIM / 4;
    for (int t = i; t < nj; t += stride) {
        uint2 H, L;
        split_bf16(((const float4*)job_h)[t], H, L);
        ((uint2*)g_job_hi)[t] = H;
        ((uint2*)g_job_lo)[t] = L;
    }
    for (int t = i; t < nm; t += stride) {
        uint2 H, L;
        split_bf16(((const float4*)machine_h)[t], H, L);
        ((uint2*)g_mach_hi)[t] = H;
        ((uint2*)g_mach_lo)[t] = L;
    }
}

// ---------------- cooperative CSR build (zero->hist->scan->fill) -------------
__global__ void __launch_bounds__(256, 4) coop_build_kernel(
    const int* __restrict__ job_idx, const int* __restrict__ mach_idx, int n_edges)
{
    cg::grid_group grid = cg::this_grid();
    int tid = threadIdx.x;
    int gid = blockIdx.x * blockDim.x + tid;
    int gstride = gridDim.x * blockDim.x;
    int lane = tid & 31, wid = tid >> 5;
    __shared__ int wsum[8];

    // phase 0: zero cursors
    for (int t = gid; t < N_JOBS; t += gstride) g_job_cur[t] = 0;
    for (int t = gid; t < N_MACH; t += gstride) g_mach_cur[t] = 0;
    grid.sync();

    // phase 1: histogram
    {
        int n4 = n_edges >> 2;
        const int4* j4 = (const int4*)job_idx;
        const int4* m4 = (const int4*)mach_idx;
        for (int e = gid; e < n4; e += gstride) {
            int4 a = __ldg(j4 + e);
            int4 b = __ldg(m4 + e);
            atomicAdd(&g_job_cur[a.x], 1);  atomicAdd(&g_job_cur[a.y], 1);
            atomicAdd(&g_job_cur[a.z], 1);  atomicAdd(&g_job_cur[a.w], 1);
            atomicAdd(&g_mach_cur[b.x], 1); atomicAdd(&g_mach_cur[b.y], 1);
            atomicAdd(&g_mach_cur[b.z], 1); atomicAdd(&g_mach_cur[b.w], 1);
        }
        int rem = n_edges & 3;
        if (gid < rem) {
            int e = (n4 << 2) + gid;
            atomicAdd(&g_job_cur[__ldg(job_idx + e)], 1);
            atomicAdd(&g_mach_cur[__ldg(mach_idx + e)], 1);
        }
    }
    grid.sync();

    // phase 2: scanA
    for (int blk = blockIdx.x; blk < JB + MB; blk += gridDim.x) {
        bool is_mach = blk >= JB;
        const int* cnt = is_mach ? g_mach_cur : g_job_cur;
        int* off = is_mach ? g_mach_off : g_job_off;
        int n    = is_mach ? N_MACH : N_JOBS;
        int b    = is_mach ? (blk - JB) : blk;
        int idx = b * SCAN_CHUNK + tid * 2;
        int v0 = (idx     < n) ? cnt[idx]     : 0;
        int v1 = (idx + 1 < n) ? cnt[idx + 1] : 0;
        int tsum = v0 + v1;
        int incl = tsum;
        #pragma unroll
        for (int o = 1; o < 32; o <<= 1) {
            int t = __shfl_up_sync(0xffffffffu, incl, o);
            if (lane >= o) incl += t;
        }
        if (lane == 31) wsum[wid] = incl;
        __syncthreads();
        if (tid < 8) {
            int ws = wsum[tid];
            #pragma unroll
            for (int o = 1; o < 8; o <<= 1) {
                int t = __shfl_up_sync(0xffu, ws, o);
                if (tid >= o) ws += t;
            }
            wsum[tid] = ws;
        }
        __syncthreads();
        int base = (wid == 0 ? 0 : wsum[wid - 1]) + (incl - tsum);
        if (idx     < n) off[idx]     = base;
        if (idx + 1 < n) off[idx + 1] = base + v0;
        if (tid == 255) g_bsum[blk] = wsum[7];
        __syncthreads();
    }
    grid.sync();

    // phase 3: scanB
    if (blockIdx.x == 0) {
        #pragma unroll
        for (int seg = 0; seg < 2; seg++) {
            int n = seg ? MB : JB;
            int o0 = seg ? JB : 0;
            int v = (tid < n) ? g_bsum[o0 + tid] : 0;
            int incl = v;
            #pragma unroll
            for (int o = 1; o < 32; o <<= 1) {
                int t = __shfl_up_sync(0xffffffffu, incl, o);
                if (lane >= o) incl += t;
            }
            if (lane == 31) wsum[wid] = incl;
            __syncthreads();
            if (tid < 8) {
                int ws = wsum[tid];
                #pragma unroll
                for (int o = 1; o < 8; o <<= 1) {
                    int t = __shfl_up_sync(0xffu, ws, o);
                    if (tid >= o) ws += t;
                }
                wsum[tid] = ws;
            }
            __syncthreads();
            int excl = (wid == 0 ? 0 : wsum[wid - 1]) + (incl - v);
            if (tid < n) g_bsum[o0 + tid] = excl;
            __syncthreads();
        }
        if (tid == 0) { g_job_off[N_JOBS] = n_edges; g_mach_off[N_MACH] = n_edges; }
    }
    grid.sync();

    // phase 4: scanC
    for (int blk = blockIdx.x; blk < JB + MB; blk += gridDim.x) {
        bool is_mach = blk >= JB;
        int* off = is_mach ? g_mach_off : g_job_off;
        int* cur = is_mach ? g_mach_cur : g_job_cur;
        int n    = is_mach ? N_MACH : N_JOBS;
        int b    = is_mach ? (blk - JB) : blk;
        int base = g_bsum[blk];
        int idx = b * SCAN_CHUNK + tid * 2;
        if (idx < n)     { int v = off[idx]     + base; off[idx]     = v; cur[idx]     = v; }
        if (idx + 1 < n) { int v = off[idx + 1] + base; off[idx + 1] = v; cur[idx + 1] = v; }
    }
    grid.sync();

    // phase 5: fill
    {
        int n4 = n_edges >> 2;
        const int4* j4 = (const int4*)job_idx;
        const int4* m4 = (const int4*)mach_idx;
        for (int e = gid; e < n4; e += gstride) {
            int4 a = __ldg(j4 + e);
            int4 b = __ldg(m4 + e);
            int p0 = atomicAdd(&g_job_cur[a.x], 1);
            int p1 = atomicAdd(&g_job_cur[a.y], 1);
            int p2 = atomicAdd(&g_job_cur[a.z], 1);
            int p3 = atomicAdd(&g_job_cur[a.w], 1);
            int q0 = atomicAdd(&g_mach_cur[b.x], 1);
            int q1 = atomicAdd(&g_mach_cur[b.y], 1);
            int q2 = atomicAdd(&g_mach_cur[b.z], 1);
            int q3 = atomicAdd(&g_mach_cur[b.w], 1);
            g_job_nbr[p0] = b.x;  g_job_nbr[p1] = b.y;
            g_job_nbr[p2] = b.z;  g_job_nbr[p3] = b.w;
            g_mach_nbr[q0] = a.x; g_mach_nbr[q1] = a.y;
            g_mach_nbr[q2] = a.z; g_mach_nbr[q3] = a.w;
        }
        int rem = n_edges & 3;
        if (gid < rem) {
            int e = (n4 << 2) + gid;
            int j = __ldg(job_idx + e);
            int m = __ldg(mach_idx + e);
            g_job_nbr[atomicAdd(&g_job_cur[j], 1)] = m;
            g_mach_nbr[atomicAdd(&g_mach_cur[m], 1)] = j;
        }
    }
}

// Warp per row: CSR gather-mean in fp32, write result as bf16 hi/lo.
__global__ __launch_bounds__(256) void agg_kernel(const float* __restrict__ job_h,
                                                  const float* __restrict__ machine_h) {
    int gw = (blockIdx.x * blockDim.x + threadIdx.x) >> 5;
    if (gw >= N_JOBS + N_MACH) return;
    int lane = threadIdx.x & 31;
    const int* off; const int* nbr; const float* src;
    __nv_bfloat16 *dhi, *dlo; int r;
    if (gw < N_JOBS) { r = gw;          off = g_job_off;  nbr = g_job_nbr;  src = machine_h; dhi = g_jagg_hi; dlo = g_jagg_lo; }
    else             { r = gw - N_JOBS; off = g_mach_off; nbr = g_mach_nbr; src = job_h;     dhi = g_magg_hi; dlo = g_magg_lo; }
    int s = off[r], e = off[r + 1];
    int c = lane << 2;
    float4 a0 = make_float4(0.f, 0.f, 0.f, 0.f);
    float4 a1 = a0, a2 = a0, a3 = a0;
    int p = s;
    for (; p + 4 <= e; p += 4) {
        int n0 = __ldg(nbr + p);
        int n1 = __ldg(nbr + p + 1);
        int n2 = __ldg(nbr + p + 2);
        int n3 = __ldg(nbr + p + 3);
        float4 v0 = *(const float4*)(src + (size_t)n0 * DIM + c);
        float4 v1 = *(const float4*)(src + (size_t)n1 * DIM + c);
        float4 v2 = *(const float4*)(src + (size_t)n2 * DIM + c);
        float4 v3 = *(const float4*)(src + (size_t)n3 * DIM + c);
        a0.x += v0.x; a0.y += v0.y; a0.z += v0.z; a0.w += v0.w;
        a1.x += v1.x; a1.y += v1.y; a1.z += v1.z; a1.w += v1.w;
        a2.x += v2.x; a2.y += v2.y; a2.z += v2.z; a2.w += v2.w;
        a3.x += v3.x; a3.y += v3.y; a3.z += v3.z; a3.w += v3.w;
    }
    for (; p < e; p++) {
        int n0 = __ldg(nbr + p);
        float4 v0 = *(const float4*)(src + (size_t)n0 * DIM + c);
        a0.x += v0.x; a0.y += v0.y; a0.z += v0.z; a0.w += v0.w;
    }
    float idg = 1.0f / (float)max(e - s, 1);
    a0.x = (a0.x + a1.x + a2.x + a3.x) * idg;
    a0.y = (a0.y + a1.y + a2.y + a3.y) * idg;
    a0.z = (a0.z + a1.z + a2.z + a3.z) * idg;
    a0.w = (a0.w + a1.w + a2.w + a3.w) * idg;
    uint2 H, L;
    split_bf16(a0, H, L);
    *(uint2*)(dhi + (size_t)r * DIM + c) = H;
    *(uint2*)(dlo + (size_t)r * DIM + c) = L;
}

// ---------------- HMMA GEMM + ReLU + LN, cp.async double-buffered ------------
// BM=64, 512 threads / 16 warps: warp (rg = wid&3, cq = wid>>2) owns rows
// rg*16..+15 x cols cq*32..+31. Units = (tile, K-half); A staged via cp.async
// from pre-converted bf16 hi/lo tables into ping-pong buffers.

__global__ __launch_bounds__(THREADS_T, 1) void gemm_ln_kernel(
    const float* __restrict__ Wj, const float* __restrict__ bj,
    const float* __restrict__ lnsj, const float* __restrict__ lnbj,
    const float* __restrict__ Wm, const float* __restrict__ bm,
    const float* __restrict__ lnsm, const float* __restrict__ lnbm,
    float* __restrict__ out)
{
    extern __shared__ char smem[];
    uint32_t sb = smem_to_u32(smem);
    int tid = threadIdx.x;
    int wid = tid >> 5, lane = tid & 31;
    int rg = wid & 3;                        // row group (16 rows)
    int cq = wid >> 2;                       // column quarter (32 cols)
    int wr = rg * 16;
    int cb = cq * 32;

    int a_row  = lane & 15;
    int a_koff = (lane >> 4) * 8;
    int w_rsub = (lane >> 4) * 8 + (lane & 7);
    int w_koff = ((lane >> 3) & 1) * 8;

    float2* part = (float2*)(smem + SM_PART);    // [row][quarter] -> (sum, sq)
    const int abuf_hi[2] = {SM_A0HI, SM_A1HI};
    const int abuf_lo[2] = {SM_A0LO, SM_A1LO};

    for (int phase = 0; phase < 2; phase++) {
        const __nv_bfloat16* hhi = phase ? g_mach_hi : g_job_hi;
        const __nv_bfloat16* hlo = phase ? g_mach_lo : g_job_lo;
        const __nv_bfloat16* ahi = phase ? g_magg_hi : g_jagg_hi;
        const __nv_bfloat16* alo = phase ? g_magg_lo : g_jagg_lo;
        const float* W     = phase ? Wm : Wj;
        const float* bias  = phase ? bm : bj;
        const float* lns   = phase ? lnsm : lnsj;
        const float* lnb   = phase ? lnbm : lnbj;
        float* po          = phase ? (out + (size_t)N_JOBS * DIM) : out;
        int n_rows         = phase ? N_MACH : N_JOBS;
        int ntiles         = phase ? MACH_TILES : JOB_TILES;
        int units          = ntiles * 2;

        // Stage W[128][256] -> bf16 hi/lo (row stride 528B) + LN params.
        __syncthreads();
        #pragma unroll 4
        for (int it = 0; it < 16; it++) {
            int idx4 = tid + it * THREADS_T;           // 8192 float4
            int r  = idx4 >> 6;
            int c4 = (idx4 & 63) << 2;
            float4 v = *(const float4*)(W + r * KDIM + c4);
            uint2 H, L;
            split_bf16(v, H, L);
            *(uint2*)(smem + SM_WHI + r * 528 + c4 * 2) = H;
            *(uint2*)(smem + SM_WLO + r * 528 + c4 * 2) = L;
        }
        if (tid < 128) {
            ((float*)(smem + SM_BIAS))[tid] = bias[tid];
            ((float*)(smem + SM_GS))[tid]   = lns[tid];
            ((float*)(smem + SM_GB))[tid]   = lnb[tid];
        }
        __syncthreads();

        // stage unit u into buffer (u&1): 2048 x 16B cp.async, 4 per thread.
        auto stage = [&](int u) {
            int buf = u & 1;
            int tile = u >> 1;
            int half = u & 1 ^ 0;   // placeholder; real half below
            (void)half;
            int hsel = u & 1;       // NOTE: unit u = tile*2 + half -> half = u&1
            // recompute: tile = u>>1, half = u&1
            const __nv_bfloat16* shi = (u & 1) ? ahi : hhi;
            const __nv_bfloat16* slo = (u & 1) ? alo : hlo;
            (void)hsel;
            int row0 = tile * BM;
            #pragma unroll
            for (int it = 0; it < 4; it++) {
                int idx = tid + it * THREADS_T;        // 0..2047
                int arr = idx >> 10;
                int rem = idx & 1023;
                int r  = rem >> 4;
                int ck = rem & 15;
                int grow = min(row0 + r, n_rows - 1);
                const __nv_bfloat16* src = (arr ? slo : shi) + (size_t)grow * DIM + ck * 8;
                uint32_t dst = sb + (arr ? abuf_lo[buf] : abuf_hi[buf]) + r * 272 + ck * 16;
                cp_async16(dst, src);
            }
            asm volatile("cp.async.commit_group;" ::: "memory");
        };

        stage(0);
        if (units > 1) stage(1);

        float acc[4][4];
        for (int u = 0; u < units; u++) {
            int buf = u & 1;
            if (u + 1 < units) {
                asm volatile("cp.async.wait_group 1;" ::: "memory");
            } else {
                asm volatile("cp.async.wait_group 0;" ::: "memory");
            }
            __syncthreads();

            if ((u & 1) == 0) {
                #pragma unroll
                for (int nf = 0; nf < 4; nf++) {
                    acc[nf][0] = 0.f; acc[nf][1] = 0.f; acc[nf][2] = 0.f; acc[nf][3] = 0.f;
                }
            }

            int kg0 = (u & 1) * 128;
            uint32_t ah_base = sb + abuf_hi[buf];
            uint32_t al_base = sb + abuf_lo[buf];
            #pragma unroll 2
            for (int ks = 0; ks < 8; ks++) {
                int kb = ks * 16;
                uint32_t a_off = (uint32_t)((wr + a_row) * 272 + (kb + a_koff) * 2);
                uint32_t ahf[4], alf[4];
                ldsm_x4(ahf, ah_base + a_off);
                ldsm_x4(alf, al_base + a_off);
                #pragma unroll
                for (int nf2 = 0; nf2 < 2; nf2++) {
                    uint32_t w_off = (uint32_t)((cb + nf2 * 16 + w_rsub) * 528 +
                                                (kg0 + kb + w_koff) * 2);
                    uint32_t whf[4], wlf[4];
                    ldsm_x4(whf, sb + SM_WHI + w_off);
                    ldsm_x4(wlf, sb + SM_WLO + w_off);
                    mma_bf16(acc[nf2 * 2],     ahf, whf);
                    mma_bf16(acc[nf2 * 2 + 1], ahf, whf + 2);
                    mma_bf16(acc[nf2 * 2],     ahf, wlf);
                    mma_bf16(acc[nf2 * 2 + 1], ahf, wlf + 2);
                    mma_bf16(acc[nf2 * 2],     alf, whf);
                    mma_bf16(acc[nf2 * 2 + 1], alf, whf + 2);
                }
            }

            if (u & 1) {
                // Epilogue for tile u>>1.
                int row0 = (u >> 1) * BM;
                const float* bs = (const float*)(smem + SM_BIAS);
                const float* gs = (const float*)(smem + SM_GS);
                const float* gb = (const float*)(smem + SM_GB);
                int lc = (lane & 3) * 2;
                int rl0 = wr + (lane >> 2);
                int rl1 = rl0 + 8;
                float s0 = 0.f, q0 = 0.f, s1 = 0.f, q1 = 0.f;
                #pragma unroll
                for (int nf = 0; nf < 4; nf++) {
                    int c0 = cb + nf * 8 + lc;
                    float b0 = bs[c0], b1 = bs[c0 + 1];
                    float v00 = fmaxf(acc[nf][0] + b0, 0.f);
                    float v01 = fmaxf(acc[nf][1] + b1, 0.f);
                    float v10 = fmaxf(acc[nf][2] + b0, 0.f);
                    float v11 = fmaxf(acc[nf][3] + b1, 0.f);
                    s0 += v00 + v01; q0 += v00 * v00 + v01 * v01;
                    s1 += v10 + v11; q1 += v10 * v10 + v11 * v11;
                }
                s0 += __shfl_xor_sync(0xffffffffu, s0, 1);
                s0 += __shfl_xor_sync(0xffffffffu, s0, 2);
                q0 += __shfl_xor_sync(0xffffffffu, q0, 1);
                q0 += __shfl_xor_sync(0xffffffffu, q0, 2);
                s1 += __shfl_xor_sync(0xffffffffu, s1, 1);
                s1 += __shfl_xor_sync(0xffffffffu, s1, 2);
                q1 += __shfl_xor_sync(0xffffffffu, q1, 1);
                q1 += __shfl_xor_sync(0xffffffffu, q1, 2);
                if ((lane & 3) == 0) {
                    part[rl0 * 4 + cq] = make_float2(s0, q0);
                    part[rl1 * 4 + cq] = make_float2(s1, q1);
                }
                __syncthreads();

                float sum0 = 0.f, sq0 = 0.f, sum1 = 0.f, sq1 = 0.f;
                #pragma unroll
                for (int qq = 0; qq < 4; qq++) {
                    float2 p0 = part[rl0 * 4 + qq];
                    float2 p1 = part[rl1 * 4 + qq];
                    sum0 += p0.x; sq0 += p0.y;
                    sum1 += p1.x; sq1 += p1.y;
                }
                float mean0 = sum0 * (1.0f / 128.0f);
                float var0  = sq0 * (1.0f / 128.0f) - mean0 * mean0;
                float rstd0 = rsqrtf(var0 + LN_EPS);
                float mean1 = sum1 * (1.0f / 128.0f);
                float var1  = sq1 * (1.0f / 128.0f) - mean1 * mean1;
                float rstd1 = rsqrtf(var1 + LN_EPS);

                int r0 = row0 + rl0;
                int r1 = row0 + rl1;
                #pragma unroll
                for (int nf = 0; nf < 4; nf++) {
                    int c0 = cb + nf * 8 + lc;
                    float b0 = bs[c0], b1 = bs[c0 + 1];
                    float g0 = gs[c0], g1 = gs[c0 + 1];
                    float e0 = gb[c0], e1 = gb[c0 + 1];
                    if (r0 < n_rows) {
                        float v00 = fmaxf(acc[nf][0] + b0, 0.f);
                        float v01 = fmaxf(acc[nf][1] + b1, 0.f);
                        float2 o;
                        o.x = (v00 - mean0) * rstd0 * g0 + e0;
                        o.y = (v01 - mean0) * rstd0 * g1 + e1;
                        *(float2*)(po + (size_t)r0 * DIM + c0) = o;
                    }
                    if (r1 < n_rows) {
                        float v10 = fmaxf(acc[nf][2] + b0, 0.f);
                        float v11 = fmaxf(acc[nf][3] + b1, 0.f);
                        float2 o;
                        o.x = (v10 - mean1) * rstd1 * g0 + e0;
                        o.y = (v11 - mean1) * rstd1 * g1 + e1;
                        *(float2*)(po + (size_t)r1 * DIM + c0) = o;
                    }
                }
            }
            __syncthreads();      // buf fully consumed (and partials read)
            if (u + 2 < units) stage(u + 2);
        }
    }
}

extern "C" void kernel_launch(void* const* d_in, const int* in_sizes, int n_in,
                              void* d_out, int out_size)
{
    const float* job_h     = (const float*)d_in[0];
    const float* machine_h = (const float*)d_in[1];
    const float* W_job_w   = (const float*)d_in[2];
    const float* W_job_b   = (const float*)d_in[3];
    const float* W_mach_w  = (const float*)d_in[4];
    const float* W_mach_b  = (const float*)d_in[5];
    const float* lnj_s     = (const float*)d_in[6];
    const float* lnj_b     = (const float*)d_in[7];
    const float* lnm_s     = (const float*)d_in[8];
    const float* lnm_b     = (const float*)d_in[9];
    const int*   job_idx   = (const int*)d_in[10];
    const int*   mach_idx  = (const int*)d_in[11];
    float* out = (float*)d_out;
    int n_edges = in_sizes[10];

    cudaFuncSetAttribute(gemm_ln_kernel, cudaFuncAttributeMaxDynamicSharedMemorySize, SM_TOTAL);

    // Launch 1: cooperative CSR build (zero folded in)
    {
        int max_blocks_per_sm = 0;
        cudaOccupancyMaxActiveBlocksPerMultiprocessor(
            &max_blocks_per_sm, coop_build_kernel, 256, 0);
        if (max_blocks_per_sm < 1) max_blocks_per_sm = 1;
        int dev = 0, n_sm = 148;
        cudaGetDevice(&dev);
        cudaDeviceGetAttribute(&n_sm, cudaDevAttrMultiProcessorCount, dev);
        int grid = n_sm * max_blocks_per_sm;
        if (grid > 592) grid = 592;
        void* cargs[] = { (void*)&job_idx, (void*)&mach_idx, (void*)&n_edges };
        cudaLaunchCooperativeKernel((const void*)coop_build_kernel,
                                    dim3(grid, 1, 1), dim3(256, 1, 1),
                                    cargs, 0, (cudaStream_t)0);
    }

    // Launch 2: convert h tables to bf16 hi/lo
    convert_kernel<<<592, 256>>>(job_h, machine_h);

    // Launch 3: CSR gather-mean (fp32 accumulate, bf16 hi/lo output)
    agg_kernel<<<(int)(((size_t)(N_JOBS + N_MACH) * 32 + 255) / 256), 256>>>(job_h, machine_h);

    // Launch 4: persistent HMMA GEMM+ReLU+LN (ncu captures launch #4)
    gemm_ln_kernel<<<148, THREADS_T, SM_TOTAL>>>(
        W_job_w, W_job_b, lnj_s, lnj_b,
        W_mach_w, W_mach_b, lnm_s, lnm_b,
        out);
}

// round 17
// speedup vs baseline: 35.8298x; 35.8298x over previous
#include <cuda_runtime.h>
#include <cuda_bf16.h>
#include <cooperative_groups.h>
#include <cstdint>
#include <cstddef>

namespace cg = cooperative_groups;

#define N_JOBS 100000
#define N_MACH 10000
#define DIM 128
#define KDIM 256
#define BM 64
#define THREADS_T 512
#define LN_EPS 1e-5f
#define MAX_EDGES 1600000

#define JOB_TILES ((N_JOBS + BM - 1) / BM)    // 1563
#define MACH_TILES ((N_MACH + BM - 1) / BM)   // 157

#define SCAN_CHUNK 512
#define JB ((N_JOBS + SCAN_CHUNK - 1) / SCAN_CHUNK)   // 196
#define MB ((N_MACH + SCAN_CHUNK - 1) / SCAN_CHUNK)   // 20

// smem layout. W rows 528B stride, A rows 272B stride (both +4-bank/row ->
// conflict-free ldmatrix). Double-buffered A halves (hi+lo each).
#define SM_BIAS 16
#define SM_GS   528
#define SM_GB   1040
#define SM_PART 2048                       // 64 rows x 4 quarters x float2 = 2KB
#define SM_WHI  4096
#define SM_WLO  (SM_WHI + 128 * 528)       //  71680
#define SM_A0HI (SM_WLO + 128 * 528)       // 139264
#define SM_A0LO (SM_A0HI + 64 * 272)       // 156672
#define SM_A1HI (SM_A0LO + 64 * 272)       // 174080
#define SM_A1LO (SM_A1HI + 64 * 272)       // 191488
#define SM_TOTAL (SM_A1LO + 64 * 272)      // 208896

// Scratch device globals: CSR ~14MB + bf16 hi/lo tables ~112MB.
__device__ int g_job_off[N_JOBS + 1];
__device__ int g_mach_off[N_MACH + 1];
__device__ int g_job_cur[N_JOBS];
__device__ int g_mach_cur[N_MACH];
__device__ int g_job_nbr[MAX_EDGES];
__device__ int g_mach_nbr[MAX_EDGES];
__device__ int g_bsum[JB + MB];
__device__ __align__(256) __nv_bfloat16 g_job_hi[(size_t)N_JOBS * DIM];
__device__ __align__(256) __nv_bfloat16 g_job_lo[(size_t)N_JOBS * DIM];
__device__ __align__(256) __nv_bfloat16 g_mach_hi[(size_t)N_MACH * DIM];
__device__ __align__(256) __nv_bfloat16 g_mach_lo[(size_t)N_MACH * DIM];
__device__ __align__(256) __nv_bfloat16 g_jagg_hi[(size_t)N_JOBS * DIM];
__device__ __align__(256) __nv_bfloat16 g_jagg_lo[(size_t)N_JOBS * DIM];
__device__ __align__(256) __nv_bfloat16 g_magg_hi[(size_t)N_MACH * DIM];
__device__ __align__(256) __nv_bfloat16 g_magg_lo[(size_t)N_MACH * DIM];

// ---------------- helpers ----------------------------------------------------
__device__ __forceinline__ uint32_t smem_to_u32(const void* p) {
    uint32_t a;
    asm("{ .reg .u64 t; cvta.to.shared.u64 t, %1; cvt.u32.u64 %0, t; }" : "=r"(a) : "l"(p));
    return a;
}
__device__ __forceinline__ void ldsm_x4(uint32_t* r, uint32_t addr) {
    asm volatile("ldmatrix.sync.aligned.m8n8.x4.shared.b16 {%0,%1,%2,%3}, [%4];"
        : "=r"(r[0]), "=r"(r[1]), "=r"(r[2]), "=r"(r[3]) : "r"(addr));
}
__device__ __forceinline__ void mma_bf16(float* c, const uint32_t* a, const uint32_t* b) {
    asm volatile(
        "mma.sync.aligned.m16n8k16.row.col.f32.bf16.bf16.f32 "
        "{%0,%1,%2,%3}, {%4,%5,%6,%7}, {%8,%9}, {%0,%1,%2,%3};"
        : "+f"(c[0]), "+f"(c[1]), "+f"(c[2]), "+f"(c[3])
        : "r"(a[0]), "r"(a[1]), "r"(a[2]), "r"(a[3]), "r"(b[0]), "r"(b[1]));
}
__device__ __forceinline__ void cp_async16(uint32_t dst, const void* src) {
    asm volatile("cp.async.cg.shared.global [%0], [%1], 16;" :: "r"(dst), "l"(src));
}
// fp32x4 -> hi bf16x4 + lo bf16x4 (lo = round(x - hi)).
__device__ __forceinline__ void split_bf16(float4 v, uint2& H, uint2& L) {
    __nv_bfloat162 h01 = __floats2bfloat162_rn(v.x, v.y);
    __nv_bfloat162 h23 = __floats2bfloat162_rn(v.z, v.w);
    float2 f01 = __bfloat1622float2(h01);
    float2 f23 = __bfloat1622float2(h23);
    __nv_bfloat162 l01 = __floats2bfloat162_rn(v.x - f01.x, v.y - f01.y);
    __nv_bfloat162 l23 = __floats2bfloat162_rn(v.z - f23.x, v.w - f23.y);
    H.x = *(unsigned*)&h01; H.y = *(unsigned*)&h23;
    L.x = *(unsigned*)&l01; L.y = *(unsigned*)&l23;
}

// ---------------- convert h tables to bf16 hi/lo -----------------------------
__global__ void convert_kernel(const float* __restrict__ job_h,
                               const float* __restrict__ machine_h) {
    int i = blockIdx.x * blockDim.x + threadIdx.x;
    int stride = gridDim.x * blockDim.x;
    const int nj = N_JOBS * DIM / 4, nm = N_MACH * DIM / 4;
    for (int t = i; t < nj; t += stride) {
        uint2 H, L;
        split_bf16(((const float4*)job_h)[t], H, L);
        ((uint2*)g_job_hi)[t] = H;
        ((uint2*)g_job_lo)[t] = L;
    }
    for (int t = i; t < nm; t += stride) {
        uint2 H, L;
        split_bf16(((const float4*)machine_h)[t], H, L);
        ((uint2*)g_mach_hi)[t] = H;
        ((uint2*)g_mach_lo)[t] = L;
    }
}

// ---------------- cooperative CSR build (zero->hist->scan->fill) -------------
__global__ void __launch_bounds__(256, 4) coop_build_kernel(
    const int* __restrict__ job_idx, const int* __restrict__ mach_idx, int n_edges)
{
    cg::grid_group grid = cg::this_grid();
    int tid = threadIdx.x;
    int gid = blockIdx.x * blockDim.x + tid;
    int gstride = gridDim.x * blockDim.x;
    int lane = tid & 31, wid = tid >> 5;
    __shared__ int wsum[8];

    // phase 0: zero cursors
    for (int t = gid; t < N_JOBS; t += gstride) g_job_cur[t] = 0;
    for (int t = gid; t < N_MACH; t += gstride) g_mach_cur[t] = 0;
    grid.sync();

    // phase 1: histogram
    {
        int n4 = n_edges >> 2;
        const int4* j4 = (const int4*)job_idx;
        const int4* m4 = (const int4*)mach_idx;
        for (int e = gid; e < n4; e += gstride) {
            int4 a = __ldg(j4 + e);
            int4 b = __ldg(m4 + e);
            atomicAdd(&g_job_cur[a.x], 1);  atomicAdd(&g_job_cur[a.y], 1);
            atomicAdd(&g_job_cur[a.z], 1);  atomicAdd(&g_job_cur[a.w], 1);
            atomicAdd(&g_mach_cur[b.x], 1); atomicAdd(&g_mach_cur[b.y], 1);
            atomicAdd(&g_mach_cur[b.z], 1); atomicAdd(&g_mach_cur[b.w], 1);
        }
        int rem = n_edges & 3;
        if (gid < rem) {
            int e = (n4 << 2) + gid;
            atomicAdd(&g_job_cur[__ldg(job_idx + e)], 1);
            atomicAdd(&g_mach_cur[__ldg(mach_idx + e)], 1);
        }
    }
    grid.sync();

    // phase 2: scanA
    for (int blk = blockIdx.x; blk < JB + MB; blk += gridDim.x) {
        bool is_mach = blk >= JB;
        const int* cnt = is_mach ? g_mach_cur : g_job_cur;
        int* off = is_mach ? g_mach_off : g_job_off;
        int n    = is_mach ? N_MACH : N_JOBS;
        int b    = is_mach ? (blk - JB) : blk;
        int idx = b * SCAN_CHUNK + tid * 2;
        int v0 = (idx     < n) ? cnt[idx]     : 0;
        int v1 = (idx + 1 < n) ? cnt[idx + 1] : 0;
        int tsum = v0 + v1;
        int incl = tsum;
        #pragma unroll
        for (int o = 1; o < 32; o <<= 1) {
            int t = __shfl_up_sync(0xffffffffu, incl, o);
            if (lane >= o) incl += t;
        }
        if (lane == 31) wsum[wid] = incl;
        __syncthreads();
        if (tid < 8) {
            int ws = wsum[tid];
            #pragma unroll
            for (int o = 1; o < 8; o <<= 1) {
                int t = __shfl_up_sync(0xffu, ws, o);
                if (tid >= o) ws += t;
            }
            wsum[tid] = ws;
        }
        __syncthreads();
        int base = (wid == 0 ? 0 : wsum[wid - 1]) + (incl - tsum);
        if (idx     < n) off[idx]     = base;
        if (idx + 1 < n) off[idx + 1] = base + v0;
        if (tid == 255) g_bsum[blk] = wsum[7];
        __syncthreads();
    }
    grid.sync();

    // phase 3: scanB
    if (blockIdx.x == 0) {
        #pragma unroll
        for (int seg = 0; seg < 2; seg++) {
            int n = seg ? MB : JB;
            int o0 = seg ? JB : 0;
            int v = (tid < n) ? g_bsum[o0 + tid] : 0;
            int incl = v;
            #pragma unroll
            for (int o = 1; o < 32; o <<= 1) {
                int t = __shfl_up_sync(0xffffffffu, incl, o);
                if (lane >= o) incl += t;
            }
            if (lane == 31) wsum[wid] = incl;
            __syncthreads();
            if (tid < 8) {
                int ws = wsum[tid];
                #pragma unroll
                for (int o = 1; o < 8; o <<= 1) {
                    int t = __shfl_up_sync(0xffu, ws, o);
                    if (tid >= o) ws += t;
                }
                wsum[tid] = ws;
            }
            __syncthreads();
            int excl = (wid == 0 ? 0 : wsum[wid - 1]) + (incl - v);
            if (tid < n) g_bsum[o0 + tid] = excl;
            __syncthreads();
        }
        if (tid == 0) { g_job_off[N_JOBS] = n_edges; g_mach_off[N_MACH] = n_edges; }
    }
    grid.sync();

    // phase 4: scanC
    for (int blk = blockIdx.x; blk < JB + MB; blk += gridDim.x) {
        bool is_mach = blk >= JB;
        int* off = is_mach ? g_mach_off : g_job_off;
        int* cur = is_mach ? g_mach_cur : g_job_cur;
        int n    = is_mach ? N_MACH : N_JOBS;
        int b    = is_mach ? (blk - JB) : blk;
        int base = g_bsum[blk];
        int idx = b * SCAN_CHUNK + tid * 2;
        if (idx < n)     { int v = off[idx]     + base; off[idx]     = v; cur[idx]     = v; }
        if (idx + 1 < n) { int v = off[idx + 1] + base; off[idx + 1] = v; cur[idx + 1] = v; }
    }
    grid.sync();

    // phase 5: fill
    {
        int n4 = n_edges >> 2;
        const int4* j4 = (const int4*)job_idx;
        const int4* m4 = (const int4*)mach_idx;
        for (int e = gid; e < n4; e += gstride) {
            int4 a = __ldg(j4 + e);
            int4 b = __ldg(m4 + e);
            int p0 = atomicAdd(&g_job_cur[a.x], 1);
            int p1 = atomicAdd(&g_job_cur[a.y], 1);
            int p2 = atomicAdd(&g_job_cur[a.z], 1);
            int p3 = atomicAdd(&g_job_cur[a.w], 1);
            int q0 = atomicAdd(&g_mach_cur[b.x], 1);
            int q1 = atomicAdd(&g_mach_cur[b.y], 1);
            int q2 = atomicAdd(&g_mach_cur[b.z], 1);
            int q3 = atomicAdd(&g_mach_cur[b.w], 1);
            g_job_nbr[p0] = b.x;  g_job_nbr[p1] = b.y;
            g_job_nbr[p2] = b.z;  g_job_nbr[p3] = b.w;
            g_mach_nbr[q0] = a.x; g_mach_nbr[q1] = a.y;
            g_mach_nbr[q2] = a.z; g_mach_nbr[q3] = a.w;
        }
        int rem = n_edges & 3;
        if (gid < rem) {
            int e = (n4 << 2) + gid;
            int j = __ldg(job_idx + e);
            int m = __ldg(mach_idx + e);
            g_job_nbr[atomicAdd(&g_job_cur[j], 1)] = m;
            g_mach_nbr[atomicAdd(&g_mach_cur[m], 1)] = j;
        }
    }
}

// Warp per row: CSR gather-mean in fp32, write result as bf16 hi/lo.
__global__ __launch_bounds__(256) void agg_kernel(const float* __restrict__ job_h,
                                                  const float* __restrict__ machine_h) {
    int gw = (blockIdx.x * blockDim.x + threadIdx.x) >> 5;
    if (gw >= N_JOBS + N_MACH) return;
    int lane = threadIdx.x & 31;
    const int* off; const int* nbr; const float* src;
    __nv_bfloat16 *dhi, *dlo; int r;
    if (gw < N_JOBS) { r = gw;          off = g_job_off;  nbr = g_job_nbr;  src = machine_h; dhi = g_jagg_hi; dlo = g_jagg_lo; }
    else             { r = gw - N_JOBS; off = g_mach_off; nbr = g_mach_nbr; src = job_h;     dhi = g_magg_hi; dlo = g_magg_lo; }
    int s = off[r], e = off[r + 1];
    int c = lane << 2;
    float4 a0 = make_float4(0.f, 0.f, 0.f, 0.f);
    float4 a1 = a0, a2 = a0, a3 = a0;
    int p = s;
    for (; p + 4 <= e; p += 4) {
        int n0 = __ldg(nbr + p);
        int n1 = __ldg(nbr + p + 1);
        int n2 = __ldg(nbr + p + 2);
        int n3 = __ldg(nbr + p + 3);
        float4 v0 = *(const float4*)(src + (size_t)n0 * DIM + c);
        float4 v1 = *(const float4*)(src + (size_t)n1 * DIM + c);
        float4 v2 = *(const float4*)(src + (size_t)n2 * DIM + c);
        float4 v3 = *(const float4*)(src + (size_t)n3 * DIM + c);
        a0.x += v0.x; a0.y += v0.y; a0.z += v0.z; a0.w += v0.w;
        a1.x += v1.x; a1.y += v1.y; a1.z += v1.z; a1.w += v1.w;
        a2.x += v2.x; a2.y += v2.y; a2.z += v2.z; a2.w += v2.w;
        a3.x += v3.x; a3.y += v3.y; a3.z += v3.z; a3.w += v3.w;
    }
    for (; p < e; p++) {
        int n0 = __ldg(nbr + p);
        float4 v0 = *(const float4*)(src + (size_t)n0 * DIM + c);
        a0.x += v0.x; a0.y += v0.y; a0.z += v0.z; a0.w += v0.w;
    }
    float idg = 1.0f / (float)max(e - s, 1);
    a0.x = (a0.x + a1.x + a2.x + a3.x) * idg;
    a0.y = (a0.y + a1.y + a2.y + a3.y) * idg;
    a0.z = (a0.z + a1.z + a2.z + a3.z) * idg;
    a0.w = (a0.w + a1.w + a2.w + a3.w) * idg;
    uint2 H, L;
    split_bf16(a0, H, L);
    *(uint2*)(dhi + (size_t)r * DIM + c) = H;
    *(uint2*)(dlo + (size_t)r * DIM + c) = L;
}

// ---------------- HMMA GEMM + ReLU + LN, cp.async double-buffered ------------
// BM=64, 512 threads / 16 warps: warp (rg = wid&3, cq = wid>>2) owns rows
// rg*16..+15 x cols cq*32..+31. Each block owns tiles blockIdx.x + k*gridDim.x
// (grid-stride). Local unit v -> tile = blockIdx.x + (v>>1)*gridDim.x,
// half = v&1. A staged via cp.async from pre-converted bf16 hi/lo tables.

__global__ __launch_bounds__(THREADS_T, 1) void gemm_ln_kernel(
    const float* __restrict__ Wj, const float* __restrict__ bj,
    const float* __restrict__ lnsj, const float* __restrict__ lnbj,
    const float* __restrict__ Wm, const float* __restrict__ bm,
    const float* __restrict__ lnsm, const float* __restrict__ lnbm,
    float* __restrict__ out)
{
    extern __shared__ char smem[];
    uint32_t sb = smem_to_u32(smem);
    int tid = threadIdx.x;
    int wid = tid >> 5, lane = tid & 31;
    int rg = wid & 3;                        // row group (16 rows)
    int cq = wid >> 2;                       // column quarter (32 cols)
    int wr = rg * 16;
    int cb = cq * 32;

    int a_row  = lane & 15;
    int a_koff = (lane >> 4) * 8;
    int w_rsub = (lane >> 4) * 8 + (lane & 7);
    int w_koff = ((lane >> 3) & 1) * 8;

    float2* part = (float2*)(smem + SM_PART);    // [row][quarter] -> (sum, sq)
    const int abuf_hi[2] = {SM_A0HI, SM_A1HI};
    const int abuf_lo[2] = {SM_A0LO, SM_A1LO};

    for (int phase = 0; phase < 2; phase++) {
        const __nv_bfloat16* hhi = phase ? g_mach_hi : g_job_hi;
        const __nv_bfloat16* hlo = phase ? g_mach_lo : g_job_lo;
        const __nv_bfloat16* ahi = phase ? g_magg_hi : g_jagg_hi;
        const __nv_bfloat16* alo = phase ? g_magg_lo : g_jagg_lo;
        const float* W     = phase ? Wm : Wj;
        const float* bias  = phase ? bm : bj;
        const float* lns   = phase ? lnsm : lnsj;
        const float* lnb   = phase ? lnbm : lnbj;
        float* po          = phase ? (out + (size_t)N_JOBS * DIM) : out;
        int n_rows         = phase ? N_MACH : N_JOBS;
        int ntiles         = phase ? MACH_TILES : JOB_TILES;

        // This block's tile count (grid-stride ownership) -> local units.
        int nloc = ((int)blockIdx.x < ntiles)
                     ? ((ntiles - 1 - (int)blockIdx.x) / (int)gridDim.x + 1) : 0;
        int units = nloc * 2;

        // Stage W[128][256] -> bf16 hi/lo (row stride 528B) + LN params.
        __syncthreads();
        #pragma unroll 4
        for (int it = 0; it < 16; it++) {
            int idx4 = tid + it * THREADS_T;           // 8192 float4
            int r  = idx4 >> 6;
            int c4 = (idx4 & 63) << 2;
            float4 v = *(const float4*)(W + r * KDIM + c4);
            uint2 H, L;
            split_bf16(v, H, L);
            *(uint2*)(smem + SM_WHI + r * 528 + c4 * 2) = H;
            *(uint2*)(smem + SM_WLO + r * 528 + c4 * 2) = L;
        }
        if (tid < 128) {
            ((float*)(smem + SM_BIAS))[tid] = bias[tid];
            ((float*)(smem + SM_GS))[tid]   = lns[tid];
            ((float*)(smem + SM_GB))[tid]   = lnb[tid];
        }
        __syncthreads();

        // stage local unit v into buffer (v&1): 2048 x 16B cp.async.
        auto stage = [&](int v) {
            int buf = v & 1;
            int tile = blockIdx.x + (v >> 1) * gridDim.x;
            const __nv_bfloat16* shi = (v & 1) ? ahi : hhi;
            const __nv_bfloat16* slo = (v & 1) ? alo : hlo;
            int row0 = tile * BM;
            #pragma unroll
            for (int it = 0; it < 4; it++) {
                int idx = tid + it * THREADS_T;        // 0..2047
                int arr = idx >> 10;
                int rem = idx & 1023;
                int r  = rem >> 4;
                int ck = rem & 15;
                int grow = min(row0 + r, n_rows - 1);
                const __nv_bfloat16* src = (arr ? slo : shi) + (size_t)grow * DIM + ck * 8;
                uint32_t dst = sb + (arr ? abuf_lo[buf] : abuf_hi[buf]) + r * 272 + ck * 16;
                cp_async16(dst, src);
            }
            asm volatile("cp.async.commit_group;" ::: "memory");
        };

        if (units > 0) stage(0);
        if (units > 1) stage(1);

        float acc[4][4];
        for (int u = 0; u < units; u++) {
            int buf = u & 1;
            if (u + 1 < units) {
                asm volatile("cp.async.wait_group 1;" ::: "memory");
            } else {
                asm volatile("cp.async.wait_group 0;" ::: "memory");
            }
            __syncthreads();

            if ((u & 1) == 0) {
                #pragma unroll
                for (int nf = 0; nf < 4; nf++) {
                    acc[nf][0] = 0.f; acc[nf][1] = 0.f; acc[nf][2] = 0.f; acc[nf][3] = 0.f;
                }
            }

            int kg0 = (u & 1) * 128;
            uint32_t ah_base = sb + abuf_hi[buf];
            uint32_t al_base = sb + abuf_lo[buf];
            #pragma unroll 2
            for (int ks = 0; ks < 8; ks++) {
                int kb = ks * 16;
                uint32_t a_off = (uint32_t)((wr + a_row) * 272 + (kb + a_koff) * 2);
                uint32_t ahf[4], alf[4];
                ldsm_x4(ahf, ah_base + a_off);
                ldsm_x4(alf, al_base + a_off);
                #pragma unroll
                for (int nf2 = 0; nf2 < 2; nf2++) {
                    uint32_t w_off = (uint32_t)((cb + nf2 * 16 + w_rsub) * 528 +
                                                (kg0 + kb + w_koff) * 2);
                    uint32_t whf[4], wlf[4];
                    ldsm_x4(whf, sb + SM_WHI + w_off);
                    ldsm_x4(wlf, sb + SM_WLO + w_off);
                    mma_bf16(acc[nf2 * 2],     ahf, whf);
                    mma_bf16(acc[nf2 * 2 + 1], ahf, whf + 2);
                    mma_bf16(acc[nf2 * 2],     ahf, wlf);
                    mma_bf16(acc[nf2 * 2 + 1], ahf, wlf + 2);
                    mma_bf16(acc[nf2 * 2],     alf, whf);
                    mma_bf16(acc[nf2 * 2 + 1], alf, whf + 2);
                }
            }

            if (u & 1) {
                // Epilogue for this block's tile (u>>1).
                int row0 = (blockIdx.x + (u >> 1) * gridDim.x) * BM;
                const float* bs = (const float*)(smem + SM_BIAS);
                const float* gs = (const float*)(smem + SM_GS);
                const float* gb = (const float*)(smem + SM_GB);
                int lc = (lane & 3) * 2;
                int rl0 = wr + (lane >> 2);
                int rl1 = rl0 + 8;
                float s0 = 0.f, q0 = 0.f, s1 = 0.f, q1 = 0.f;
                #pragma unroll
                for (int nf = 0; nf < 4; nf++) {
                    int c0 = cb + nf * 8 + lc;
                    float b0 = bs[c0], b1 = bs[c0 + 1];
                    float v00 = fmaxf(acc[nf][0] + b0, 0.f);
                    float v01 = fmaxf(acc[nf][1] + b1, 0.f);
                    float v10 = fmaxf(acc[nf][2] + b0, 0.f);
                    float v11 = fmaxf(acc[nf][3] + b1, 0.f);
                    s0 += v00 + v01; q0 += v00 * v00 + v01 * v01;
                    s1 += v10 + v11; q1 += v10 * v10 + v11 * v11;
                }
                s0 += __shfl_xor_sync(0xffffffffu, s0, 1);
                s0 += __shfl_xor_sync(0xffffffffu, s0, 2);
                q0 += __shfl_xor_sync(0xffffffffu, q0, 1);
                q0 += __shfl_xor_sync(0xffffffffu, q0, 2);
                s1 += __shfl_xor_sync(0xffffffffu, s1, 1);
                s1 += __shfl_xor_sync(0xffffffffu, s1, 2);
                q1 += __shfl_xor_sync(0xffffffffu, q1, 1);
                q1 += __shfl_xor_sync(0xffffffffu, q1, 2);
                if ((lane & 3) == 0) {
                    part[rl0 * 4 + cq] = make_float2(s0, q0);
                    part[rl1 * 4 + cq] = make_float2(s1, q1);
                }
                __syncthreads();

                float sum0 = 0.f, sq0 = 0.f, sum1 = 0.f, sq1 = 0.f;
                #pragma unroll
                for (int qq = 0; qq < 4; qq++) {
                    float2 p0 = part[rl0 * 4 + qq];
                    float2 p1 = part[rl1 * 4 + qq];
                    sum0 += p0.x; sq0 += p0.y;
                    sum1 += p1.x; sq1 += p1.y;
                }
                float mean0 = sum0 * (1.0f / 128.0f);
                float var0  = sq0 * (1.0f / 128.0f) - mean0 * mean0;
                float rstd0 = rsqrtf(var0 + LN_EPS);
                float mean1 = sum1 * (1.0f / 128.0f);
                float var1  = sq1 * (1.0f / 128.0f) - mean1 * mean1;
                float rstd1 = rsqrtf(var1 + LN_EPS);

                int r0 = row0 + rl0;
                int r1 = row0 + rl1;
                #pragma unroll
                for (int nf = 0; nf < 4; nf++) {
                    int c0 = cb + nf * 8 + lc;
                    float b0 = bs[c0], b1 = bs[c0 + 1];
                    float g0 = gs[c0], g1 = gs[c0 + 1];
                    float e0 = gb[c0], e1 = gb[c0 + 1];
                    if (r0 < n_rows) {
                        float v00 = fmaxf(acc[nf][0] + b0, 0.f);
                        float v01 = fmaxf(acc[nf][1] + b1, 0.f);
                        float2 o;
                        o.x = (v00 - mean0) * rstd0 * g0 + e0;
                        o.y = (v01 - mean0) * rstd0 * g1 + e1;
                        *(float2*)(po + (size_t)r0 * DIM + c0) = o;
                    }
                    if (r1 < n_rows) {
                        float v10 = fmaxf(acc[nf][2] + b0, 0.f);
                        float v11 = fmaxf(acc[nf][3] + b1, 0.f);
                        float2 o;
                        o.x = (v10 - mean1) * rstd1 * g0 + e0;
                        o.y = (v11 - mean1) * rstd1 * g1 + e1;
                        *(float2*)(po + (size_t)r1 * DIM + c0) = o;
                    }
                }
            }
            __syncthreads();      // buf fully consumed (and partials read)
            if (u + 2 < units) stage(u + 2);
        }
    }
}

extern "C" void kernel_launch(void* const* d_in, const int* in_sizes, int n_in,
                              void* d_out, int out_size)
{
    const float* job_h     = (const float*)d_in[0];
    const float* machine_h = (const float*)d_in[1];
    const float* W_job_w   = (const float*)d_in[2];
    const float* W_job_b   = (const float*)d_in[3];
    const float* W_mach_w  = (const float*)d_in[4];
    const float* W_mach_b  = (const float*)d_in[5];
    const float* lnj_s     = (const float*)d_in[6];
    const float* lnj_b     = (const float*)d_in[7];
    const float* lnm_s     = (const float*)d_in[8];
    const float* lnm_b     = (const float*)d_in[9];
    const int*   job_idx   = (const int*)d_in[10];
    const int*   mach_idx  = (const int*)d_in[11];
    float* out = (float*)d_out;
    int n_edges = in_sizes[10];

    cudaFuncSetAttribute(gemm_ln_kernel, cudaFuncAttributeMaxDynamicSharedMemorySize, SM_TOTAL);

    // Launch 1: cooperative CSR build (zero folded in)
    {
        int max_blocks_per_sm = 0;
        cudaOccupancyMaxActiveBlocksPerMultiprocessor(
            &max_blocks_per_sm, coop_build_kernel, 256, 0);
        if (max_blocks_per_sm < 1) max_blocks_per_sm = 1;
        int dev = 0, n_sm = 148;
        cudaGetDevice(&dev);
        cudaDeviceGetAttribute(&n_sm, cudaDevAttrMultiProcessorCount, dev);
        int grid = n_sm * max_blocks_per_sm;
        if (grid > 592) grid = 592;
        void* cargs[] = { (void*)&job_idx, (void*)&mach_idx, (void*)&n_edges };
        cudaLaunchCooperativeKernel((const void*)coop_build_kernel,
                                    dim3(grid, 1, 1), dim3(256, 1, 1),
                                    cargs, 0, (cudaStream_t)0);
    }

    // Launch 2: convert h tables to bf16 hi/lo
    convert_kernel<<<592, 256>>>(job_h, machine_h);

    // Launch 3: CSR gather-mean (fp32 accumulate, bf16 hi/lo output)
    agg_kernel<<<(int)(((size_t)(N_JOBS + N_MACH) * 32 + 255) / 256), 256>>>(job_h, machine_h);

    // Launch 4: persistent HMMA GEMM+ReLU+LN (ncu captures launch #4)
    gemm_ln_kernel<<<148, THREADS_T, SM_TOTAL>>>(
        W_job_w, W_job_b, lnj_s, lnj_b,
        W_mach_w, W_mach_b, lnm_s, lnm_b,
        out);
}